// round 7
// baseline (speedup 1.0000x reference)
#include <cuda_runtime.h>
#include <cstdint>

// ---------------------------------------------------------------------------
// Problem constants
// ---------------------------------------------------------------------------
#define NPAIRS 64      // B*heads = 8*8
#define NSEQ   4096    // H*W
#define DD     64      // head_dim
#define SPLITS 8
#define TILES  4       // tiles of 128 columns per CTA
#define OTS    140     // O^T transpose buffer stride (conflict-free, 16B-aligned)

// Scratch (device globals: no allocations allowed)
__device__ float g_scratch[NPAIRS * SPLITS * DD * DD];  // 8 MB
__device__ float g_kv[NPAIRS * DD * DD];                // 1 MB

// ---------------------------------------------------------------------------
// bf16 split helpers (Markidis-style 3-term compensation)
// ---------------------------------------------------------------------------
__device__ __forceinline__ uint32_t bf2(float lo, float hi) {
    uint32_t r;
    asm("cvt.rn.bf16x2.f32 %0, %1, %2;" : "=r"(r) : "f"(hi), "f"(lo));
    return r;
}
__device__ __forceinline__ void split2(float x0, float x1, uint32_t& h, uint32_t& l) {
    h = bf2(x0, x1);
    float h0 = __uint_as_float(h << 16);
    float h1 = __uint_as_float(h & 0xFFFF0000u);
    l = bf2(x0 - h0, x1 - h1);
}
__device__ __forceinline__ void mma_bf16(float* d, const uint32_t* a, const uint32_t* b) {
    asm volatile(
        "mma.sync.aligned.m16n8k16.row.col.f32.bf16.bf16.f32 "
        "{%0,%1,%2,%3}, {%4,%5,%6,%7}, {%8,%9}, {%0,%1,%2,%3};"
        : "+f"(d[0]), "+f"(d[1]), "+f"(d[2]), "+f"(d[3])
        : "r"(a[0]), "r"(a[1]), "r"(a[2]), "r"(a[3]), "r"(b[0]), "r"(b[1]));
}
__device__ __forceinline__ void mma3(float* d, const uint32_t* ah, const uint32_t* al,
                                     const uint32_t* bh, const uint32_t* bl) {
    mma_bf16(d, al, bh);
    mma_bf16(d, ah, bl);
    mma_bf16(d, ah, bh);
}

// ---------------------------------------------------------------------------
// cp.async helpers
// ---------------------------------------------------------------------------
__device__ __forceinline__ void cpa16(uint32_t s, const void* g) {
    asm volatile("cp.async.cg.shared.global [%0], [%1], 16;" :: "r"(s), "l"(g));
}
__device__ __forceinline__ void cpa_commit() {
    asm volatile("cp.async.commit_group;");
}
template<int N> __device__ __forceinline__ void cpa_wait() {
    asm volatile("cp.async.wait_group %0;" :: "n"(N));
}

// ---------------------------------------------------------------------------
// Kernel 1: per (pair, split of 512 cols): KF = relu(Wf@Ktile+b); KV += KF@V^T
// cp.async double-buffered raw staging; pre-split bf16 hi/lo planes in smem.
// Plane layouts identical to the validated round-6 kernel.
// ---------------------------------------------------------------------------
__global__ void __launch_bounds__(256, 1)
k_kvpass(const float* __restrict__ K, const float* __restrict__ V,
         const float* __restrict__ Wf, const float* __restrict__ bf)
{
    extern __shared__ uint32_t sm[];
    uint32_t* KpHi = sm;               // 32*136 = 4352
    uint32_t* KpLo = sm + 4352;
    uint32_t* KFHi = sm;               // alias (time-separated)
    uint32_t* KFLo = sm + 4352;
    uint32_t* VpHi = sm + 8704;        // 64*68
    uint32_t* VpLo = sm + 13056;
    uint32_t* WaHi = sm + 17408;       // 64*36
    uint32_t* WaLo = sm + 19712;
    float*    bfs  = (float*)(sm + 22016);   // 64
    float*    rawK = (float*)(sm + 22080);   // 2 bufs x 8448 (64 rows x 132)
    float*    rawV = (float*)(sm + 38976);   // 2 bufs x 8448  -> total 55872 u32

    const int p     = blockIdx.y;
    const int split = blockIdx.x;
    const int t     = threadIdx.x;
    const int w     = t >> 5;
    const int lane  = t & 31;
    const int g     = lane >> 2;
    const int q     = lane & 3;
    const int mstrip = w & 3;
    const int nh     = w >> 2;
    const int r0 = mstrip * 16 + g;
    const int r1 = r0 + 8;

    const uint32_t rawK_s = (uint32_t)__cvta_generic_to_shared(rawK);
    const uint32_t rawV_s = (uint32_t)__cvta_generic_to_shared(rawV);

    const float* Kb = K + (size_t)p * DD * NSEQ;
    const float* Vb = V + (size_t)p * DD * NSEQ;

    // prologue: prefetch tiles 0 and 1
    #pragma unroll
    for (int pt = 0; pt < 2; ++pt) {
        const int n0 = split * 512 + pt * 128;
        for (int m = t; m < 64 * 32; m += 256) {
            const int row = m >> 5, c4 = (m & 31) << 2;
            const uint32_t so = (uint32_t)(pt * 8448 + row * 132 + c4) << 2;
            cpa16(rawK_s + so, Kb + row * NSEQ + n0 + c4);
            cpa16(rawV_s + so, Vb + row * NSEQ + n0 + c4);
        }
        cpa_commit();
    }

    // Wf planes + bias (overlaps with prefetch)
    for (int i = t; i < 64 * 32; i += 256) {
        const int e = i >> 5, dp = i & 31;
        float2 f = *(const float2*)&Wf[e * 64 + 2 * dp];
        uint32_t h, l; split2(f.x, f.y, h, l);
        WaHi[e * 36 + dp] = h; WaLo[e * 36 + dp] = l;
    }
    if (t < 64) bfs[t] = bf[t];

    float kv[4][4];
    #pragma unroll
    for (int i = 0; i < 4; ++i)
        #pragma unroll
        for (int j = 0; j < 4; ++j) kv[i][j] = 0.f;

    #pragma unroll
    for (int tile = 0; tile < TILES; ++tile) {
        const float* rK = rawK + (tile & 1) * 8448;
        const float* rV = rawV + (tile & 1) * 8448;
        if (tile == TILES - 1) cpa_wait<0>(); else cpa_wait<1>();
        __syncthreads();   // raw ready; prev GEMM2 done reading planes; Wa/bfs visible

        // split raw -> planes
        for (int m = t; m < 32 * 32; m += 256) {
            const int dp = m >> 5;
            const int c4 = (m & 31) << 2;
            float4 k0 = *(const float4*)&rK[(2 * dp) * 132 + c4];
            float4 k1 = *(const float4*)&rK[(2 * dp + 1) * 132 + c4];
            uint32_t h[4], l[4];
            split2(k0.x, k1.x, h[0], l[0]);
            split2(k0.y, k1.y, h[1], l[1]);
            split2(k0.z, k1.z, h[2], l[2]);
            split2(k0.w, k1.w, h[3], l[3]);
            *(uint4*)&KpHi[dp * 136 + c4] = make_uint4(h[0], h[1], h[2], h[3]);
            *(uint4*)&KpLo[dp * 136 + c4] = make_uint4(l[0], l[1], l[2], l[3]);
        }
        for (int m = t; m < 64 * 32; m += 256) {
            const int row = m >> 5;
            const int c4  = (m & 31) << 2;
            float4 v = *(const float4*)&rV[row * 132 + c4];
            uint32_t h0, l0, h1, l1;
            split2(v.x, v.y, h0, l0);
            split2(v.z, v.w, h1, l1);
            *(uint2*)&VpHi[row * 68 + (c4 >> 1)] = make_uint2(h0, h1);
            *(uint2*)&VpLo[row * 68 + (c4 >> 1)] = make_uint2(l0, l1);
        }
        __syncthreads();   // planes ready, raw buffer consumed

        // prefetch tile+2 into the buffer just freed
        if (tile + 2 < TILES) {
            const int n0n = split * 512 + (tile + 2) * 128;
            for (int m = t; m < 64 * 32; m += 256) {
                const int row = m >> 5, c4 = (m & 31) << 2;
                const uint32_t so = (uint32_t)((tile & 1) * 8448 + row * 132 + c4) << 2;
                cpa16(rawK_s + so, Kb + row * NSEQ + n0n + c4);
                cpa16(rawV_s + so, Vb + row * NSEQ + n0n + c4);
            }
            cpa_commit();
        }

        // ---- GEMM1: KF = Wf @ Ktile (M=64, N=128, K=64) ----
        float acc[8][4];
        #pragma unroll
        for (int i = 0; i < 8; ++i)
            #pragma unroll
            for (int j = 0; j < 4; ++j) acc[i][j] = 0.f;

        #pragma unroll
        for (int ks = 0; ks < 4; ++ks) {
            const int dp0 = ks * 8 + q;
            uint32_t ah[4], al[4];
            ah[0] = WaHi[r0 * 36 + dp0];     al[0] = WaLo[r0 * 36 + dp0];
            ah[1] = WaHi[r1 * 36 + dp0];     al[1] = WaLo[r1 * 36 + dp0];
            ah[2] = WaHi[r0 * 36 + dp0 + 4]; al[2] = WaLo[r0 * 36 + dp0 + 4];
            ah[3] = WaHi[r1 * 36 + dp0 + 4]; al[3] = WaLo[r1 * 36 + dp0 + 4];
            #pragma unroll
            for (int nf = 0; nf < 8; ++nf) {
                const int c = nh * 64 + nf * 8 + g;
                uint32_t bh[2], bl[2];
                bh[0] = KpHi[dp0 * 136 + c];       bl[0] = KpLo[dp0 * 136 + c];
                bh[1] = KpHi[(dp0 + 4) * 136 + c]; bl[1] = KpLo[(dp0 + 4) * 136 + c];
                mma3(acc[nf], ah, al, bh, bl);
            }
        }
        __syncthreads();   // all warps done reading Kp before KF overwrites it

        {
            const float b0 = bfs[r0], b1 = bfs[r1];
            #pragma unroll
            for (int nf = 0; nf < 8; ++nf) {
                const int np = nh * 32 + nf * 4 + q;
                uint32_t h, l;
                split2(fmaxf(acc[nf][0] + b0, 0.f), fmaxf(acc[nf][1] + b0, 0.f), h, l);
                KFHi[r0 * 68 + np] = h; KFLo[r0 * 68 + np] = l;
                split2(fmaxf(acc[nf][2] + b1, 0.f), fmaxf(acc[nf][3] + b1, 0.f), h, l);
                KFHi[r1 * 68 + np] = h; KFLo[r1 * 68 + np] = l;
            }
        }
        __syncthreads();

        // ---- GEMM2: KV += KF @ V^T (M=64, N=64, K=128) ----
        #pragma unroll
        for (int ks = 0; ks < 8; ++ks) {
            const int np0 = ks * 8 + q;
            uint32_t ah[4], al[4];
            ah[0] = KFHi[r0 * 68 + np0];     al[0] = KFLo[r0 * 68 + np0];
            ah[1] = KFHi[r1 * 68 + np0];     al[1] = KFLo[r1 * 68 + np0];
            ah[2] = KFHi[r0 * 68 + np0 + 4]; al[2] = KFLo[r0 * 68 + np0 + 4];
            ah[3] = KFHi[r1 * 68 + np0 + 4]; al[3] = KFLo[r1 * 68 + np0 + 4];
            #pragma unroll
            for (int ef = 0; ef < 4; ++ef) {
                const int row = nh * 32 + ef * 8 + g;
                uint32_t bh[2], bl[2];
                bh[0] = VpHi[row * 68 + np0];     bl[0] = VpLo[row * 68 + np0];
                bh[1] = VpHi[row * 68 + np0 + 4]; bl[1] = VpLo[row * 68 + np0 + 4];
                mma3(kv[ef], ah, al, bh, bl);
            }
        }
    }

    float* dst = g_scratch + ((size_t)p * SPLITS + split) * DD * DD;
    #pragma unroll
    for (int ef = 0; ef < 4; ++ef) {
        const int c = nh * 32 + ef * 8 + 2 * q;
        *(float2*)&dst[r0 * DD + c] = make_float2(kv[ef][0], kv[ef][1]);
        *(float2*)&dst[r1 * DD + c] = make_float2(kv[ef][2], kv[ef][3]);
    }
}

// ---------------------------------------------------------------------------
// Kernel 2: deterministic fixed-order reduction of split partials
// ---------------------------------------------------------------------------
__global__ void k_reduce()
{
    const int idx = blockIdx.x * 256 + threadIdx.x;   // 0 .. 64*4096-1
    const int pr = idx >> 12;
    const int r  = idx & 4095;
    float s = 0.f;
    #pragma unroll
    for (int sp = 0; sp < SPLITS; ++sp)
        s += g_scratch[((size_t)pr * SPLITS + sp) * (DD * DD) + r];
    g_kv[idx] = s;
}

// ---------------------------------------------------------------------------
// Kernel 3 (transposed form, 4 tiles of 128 cols per CTA):
//   GEMM3: QF^T[n][e] = relu( Q^T[n][d] @ Wf^T[d][e] + b[e] )
//   GEMM4: O^T[n][e2] = QF^T[n][e] @ KV[e][e2]
// cp.async pipelined Q staging; output via smem transpose -> coalesced float4.
// ---------------------------------------------------------------------------
__global__ void __launch_bounds__(256, 1)
k_qpass(const float* __restrict__ Q, const float* __restrict__ Wf,
        const float* __restrict__ bf, float* __restrict__ Out)
{
    extern __shared__ uint32_t sm[];
    uint32_t* QdHi = sm;               // 32*136 = 4352
    uint32_t* QdLo = sm + 4352;
    uint32_t* QFHi = sm;               // 128*36 alias (time-separated)
    uint32_t* QFLo = sm + 4608;
    float*    Ot   = (float*)sm;       // 64*OTS = 8960 alias (time-separated)
    uint32_t* WbHi = sm + 9216;        // 32*72
    uint32_t* WbLo = sm + 11520;
    uint32_t* KVHi = sm + 13824;       // 32*72
    uint32_t* KVLo = sm + 16128;
    float*    bfs  = (float*)(sm + 18432);   // 64
    float*    rawQ = (float*)(sm + 18496);   // 2 bufs x 8448 -> total 35392 u32

    const int p   = blockIdx.y;
    const int nb0 = blockIdx.x * 512;
    const int t    = threadIdx.x;
    const int w    = t >> 5;
    const int lane = t & 31;
    const int g    = lane >> 2;
    const int q    = lane & 3;
    const int r0 = w * 16 + g;
    const int r1 = r0 + 8;

    const uint32_t rawQ_s = (uint32_t)__cvta_generic_to_shared(rawQ);
    const float* Qb = Q + (size_t)p * DD * NSEQ;

    // prologue: prefetch Q tiles 0 and 1
    #pragma unroll
    for (int pt = 0; pt < 2; ++pt) {
        const int n0 = nb0 + pt * 128;
        for (int m = t; m < 64 * 32; m += 256) {
            const int row = m >> 5, c4 = (m & 31) << 2;
            cpa16(rawQ_s + ((uint32_t)(pt * 8448 + row * 132 + c4) << 2),
                  Qb + row * NSEQ + n0 + c4);
        }
        cpa_commit();
    }

    // Wb planes
    for (int i = t; i < 64 * 32; i += 256) {
        const int e = i >> 5, dp = i & 31;
        float2 f = *(const float2*)&Wf[e * 64 + 2 * dp];
        uint32_t h, l; split2(f.x, f.y, h, l);
        WbHi[dp * 72 + e] = h; WbLo[dp * 72 + e] = l;
    }
    // KVd planes (pack along e)
    for (int i = t; i < 32 * 64; i += 256) {
        const int ep = i >> 6, e2 = i & 63;
        const float a = g_kv[(size_t)p * 4096 + (2 * ep) * 64 + e2];
        const float b = g_kv[(size_t)p * 4096 + (2 * ep + 1) * 64 + e2];
        uint32_t h, l; split2(a, b, h, l);
        KVHi[ep * 72 + e2] = h; KVLo[ep * 72 + e2] = l;
    }
    if (t < 64) bfs[t] = bf[t];

    #pragma unroll
    for (int tile = 0; tile < TILES; ++tile) {
        const int n0 = nb0 + tile * 128;
        const float* rQ = rawQ + (tile & 1) * 8448;
        if (tile == TILES - 1) cpa_wait<0>(); else cpa_wait<1>();
        __syncthreads();   // raw ready; prev STG phase done reading Ot; Wb/KV visible

        // split raw -> Qd planes
        for (int m = t; m < 32 * 32; m += 256) {
            const int dp = m >> 5;
            const int c4 = (m & 31) << 2;
            float4 q0 = *(const float4*)&rQ[(2 * dp) * 132 + c4];
            float4 q1 = *(const float4*)&rQ[(2 * dp + 1) * 132 + c4];
            uint32_t h[4], l[4];
            split2(q0.x, q1.x, h[0], l[0]);
            split2(q0.y, q1.y, h[1], l[1]);
            split2(q0.z, q1.z, h[2], l[2]);
            split2(q0.w, q1.w, h[3], l[3]);
            *(uint4*)&QdHi[dp * 136 + c4] = make_uint4(h[0], h[1], h[2], h[3]);
            *(uint4*)&QdLo[dp * 136 + c4] = make_uint4(l[0], l[1], l[2], l[3]);
        }
        __syncthreads();

        if (tile + 2 < TILES) {
            const int n0n = nb0 + (tile + 2) * 128;
            for (int m = t; m < 64 * 32; m += 256) {
                const int row = m >> 5, c4 = (m & 31) << 2;
                cpa16(rawQ_s + ((uint32_t)((tile & 1) * 8448 + row * 132 + c4) << 2),
                      Qb + row * NSEQ + n0n + c4);
            }
            cpa_commit();
        }

        // ---- GEMM3: QF^T = Q^T @ Wf^T (M=128, N=64, K=64) ----
        float acc[8][4];
        #pragma unroll
        for (int i = 0; i < 8; ++i)
            #pragma unroll
            for (int j = 0; j < 4; ++j) acc[i][j] = 0.f;

        #pragma unroll
        for (int ks = 0; ks < 4; ++ks) {
            const int dp0 = ks * 8 + q;
            uint32_t ah[4], al[4];
            ah[0] = QdHi[dp0 * 136 + r0];       al[0] = QdLo[dp0 * 136 + r0];
            ah[1] = QdHi[dp0 * 136 + r1];       al[1] = QdLo[dp0 * 136 + r1];
            ah[2] = QdHi[(dp0 + 4) * 136 + r0]; al[2] = QdLo[(dp0 + 4) * 136 + r0];
            ah[3] = QdHi[(dp0 + 4) * 136 + r1]; al[3] = QdLo[(dp0 + 4) * 136 + r1];
            #pragma unroll
            for (int nf = 0; nf < 8; ++nf) {
                const int c = nf * 8 + g;
                uint32_t bh[2], bl[2];
                bh[0] = WbHi[dp0 * 72 + c];       bl[0] = WbLo[dp0 * 72 + c];
                bh[1] = WbHi[(dp0 + 4) * 72 + c]; bl[1] = WbLo[(dp0 + 4) * 72 + c];
                mma3(acc[nf], ah, al, bh, bl);
            }
        }
        __syncthreads();   // all warps done reading Qd before QF overwrites it

        // epilogue: bias (per e = column) + relu, split, store QF planes
        #pragma unroll
        for (int nf = 0; nf < 8; ++nf) {
            const int e0 = nf * 8 + 2 * q;
            const float b0 = bfs[e0], b1 = bfs[e0 + 1];
            const int ep = nf * 4 + q;
            uint32_t h, l;
            split2(fmaxf(acc[nf][0] + b0, 0.f), fmaxf(acc[nf][1] + b1, 0.f), h, l);
            QFHi[r0 * 36 + ep] = h; QFLo[r0 * 36 + ep] = l;
            split2(fmaxf(acc[nf][2] + b0, 0.f), fmaxf(acc[nf][3] + b1, 0.f), h, l);
            QFHi[r1 * 36 + ep] = h; QFLo[r1 * 36 + ep] = l;
        }
        __syncthreads();

        // ---- GEMM4: O^T = QF^T @ KV (M=128, N=64, K=64) ----
        float o[8][4];
        #pragma unroll
        for (int i = 0; i < 8; ++i)
            #pragma unroll
            for (int j = 0; j < 4; ++j) o[i][j] = 0.f;

        #pragma unroll
        for (int ks = 0; ks < 4; ++ks) {
            const int ep0 = ks * 8 + q;
            uint32_t ah[4], al[4];
            ah[0] = QFHi[r0 * 36 + ep0];     al[0] = QFLo[r0 * 36 + ep0];
            ah[1] = QFHi[r1 * 36 + ep0];     al[1] = QFLo[r1 * 36 + ep0];
            ah[2] = QFHi[r0 * 36 + ep0 + 4]; al[2] = QFLo[r0 * 36 + ep0 + 4];
            ah[3] = QFHi[r1 * 36 + ep0 + 4]; al[3] = QFLo[r1 * 36 + ep0 + 4];
            #pragma unroll
            for (int ef = 0; ef < 8; ++ef) {
                const int c = ef * 8 + g;
                uint32_t bh[2], bl[2];
                bh[0] = KVHi[ep0 * 72 + c];       bl[0] = KVLo[ep0 * 72 + c];
                bh[1] = KVHi[(ep0 + 4) * 72 + c]; bl[1] = KVLo[(ep0 + 4) * 72 + c];
                mma3(o[ef], ah, al, bh, bl);
            }
        }
        __syncthreads();   // QF reads complete before Ot overwrite

        // fragments -> Ot[e2][n_local]  (stride OTS=140: banks 24q+g, conflict-free)
        #pragma unroll
        for (int ef = 0; ef < 8; ++ef) {
            const int e2 = ef * 8 + 2 * q;
            Ot[e2 * OTS + r0]       = o[ef][0];
            Ot[(e2 + 1) * OTS + r0] = o[ef][1];
            Ot[e2 * OTS + r1]       = o[ef][2];
            Ot[(e2 + 1) * OTS + r1] = o[ef][3];
        }
        __syncthreads();

        // coalesced output: rows e2, float4 stores
        float* Ob = Out + (size_t)p * DD * NSEQ;
        for (int m = t; m < 64 * 32; m += 256) {
            const int row = m >> 5, c4 = (m & 31) << 2;
            *(float4*)(Ob + row * NSEQ + n0 + c4) = *(const float4*)&Ot[row * OTS + c4];
        }
    }
}

// ---------------------------------------------------------------------------
// Launch
// ---------------------------------------------------------------------------
extern "C" void kernel_launch(void* const* d_in, const int* in_sizes, int n_in,
                              void* d_out, int out_size)
{
    const float* q  = (const float*)d_in[0];
    const float* k  = (const float*)d_in[1];
    const float* v  = (const float*)d_in[2];
    const float* Wf = (const float*)d_in[3];
    const float* bf = (const float*)d_in[4];
    float* out = (float*)d_out;

    const int SMEM1 = 55872 * (int)sizeof(uint32_t);   // 223488 B
    const int SMEM3 = 35392 * (int)sizeof(uint32_t);   // 141568 B
    cudaFuncSetAttribute(k_kvpass, cudaFuncAttributeMaxDynamicSharedMemorySize, SMEM1);
    cudaFuncSetAttribute(k_qpass,  cudaFuncAttributeMaxDynamicSharedMemorySize, SMEM3);

    k_kvpass<<<dim3(SPLITS, NPAIRS), 256, SMEM1>>>(k, v, Wf, bf);
    k_reduce<<<(NPAIRS * DD * DD) / 256, 256>>>();
    k_qpass<<<dim3(SPLITS, NPAIRS), 256, SMEM3>>>(q, Wf, bf, out);
}